// round 1
// baseline (speedup 1.0000x reference)
#include <cuda_runtime.h>
#include <math.h>

#define T_SEQ 2048
#define H_DIM 1024
#define IN_DIM 512
#define G4 4096
#define OUT_DIM 4
#define NCTA 128
#define SLICE 8            // hidden units per CTA

#define OFF_MEAN 0
#define OFF_LSTD (T_SEQ * OUT_DIM)
#define OFF_HT   (2 * T_SEQ * OUT_DIM)
#define OFF_CT   (2 * T_SEQ * OUT_DIM + H_DIM)

// ---------------- scratch (static device memory: no allocation) ----------------
__device__ float g_gx[T_SEQ * G4];   // 32 MB: x @ w_ih.T + b_ih + b_hh
__device__ float g_ys[T_SEQ * H_DIM]; // 8 MB: LSTM hidden outputs per step
__device__ float g_h1[T_SEQ * H_DIM];
__device__ float g_h2[T_SEQ * H_DIM];
__device__ unsigned g_count;
__device__ unsigned g_gen;

__global__ void reset_kernel() {
    g_count = 0u;
    g_gen = 0u;
}

// ---------------- generic tiled GEMM: C[M,N] = A[M,K] @ B[N,K]^T + b1 (+b2), opt relu ----
#define BM 64
#define BN 64
#define BK 16

__global__ __launch_bounds__(256) void gemm_nt_kernel(
    const float* __restrict__ A, const float* __restrict__ B,
    const float* __restrict__ b1, const float* __restrict__ b2,
    float* __restrict__ C, int M, int N, int K, int relu)
{
    __shared__ float As[BM][BK + 1];
    __shared__ float Bs[BN][BK + 1];

    const int bm = blockIdx.y * BM;
    const int bn = blockIdx.x * BN;
    const int tid = threadIdx.x;
    const int tx = tid & 15;    // 0..15
    const int ty = tid >> 4;    // 0..15

    const int lr = tid >> 2;        // 0..63 tile row to load
    const int lk = (tid & 3) * 4;   // 0,4,8,12

    float acc[4][4] = {};

    for (int k0 = 0; k0 < K; k0 += BK) {
        float4 av = *(const float4*)(A + (size_t)(bm + lr) * K + k0 + lk);
        float4 bv = *(const float4*)(B + (size_t)(bn + lr) * K + k0 + lk);
        __syncthreads();
        As[lr][lk + 0] = av.x; As[lr][lk + 1] = av.y;
        As[lr][lk + 2] = av.z; As[lr][lk + 3] = av.w;
        Bs[lr][lk + 0] = bv.x; Bs[lr][lk + 1] = bv.y;
        Bs[lr][lk + 2] = bv.z; Bs[lr][lk + 3] = bv.w;
        __syncthreads();

#pragma unroll
        for (int kk = 0; kk < BK; kk++) {
            float a[4], b[4];
#pragma unroll
            for (int i = 0; i < 4; i++) a[i] = As[ty * 4 + i][kk];
#pragma unroll
            for (int j = 0; j < 4; j++) b[j] = Bs[tx * 4 + j][kk];
#pragma unroll
            for (int i = 0; i < 4; i++)
#pragma unroll
                for (int j = 0; j < 4; j++)
                    acc[i][j] = fmaf(a[i], b[j], acc[i][j]);
        }
    }

#pragma unroll
    for (int i = 0; i < 4; i++) {
        const int m = bm + ty * 4 + i;
#pragma unroll
        for (int j = 0; j < 4; j++) {
            const int n = bn + tx * 4 + j;
            float v = acc[i][j] + b1[n];
            if (b2) v += b2[n];
            if (relu) v = fmaxf(v, 0.0f);
            C[(size_t)m * N + n] = v;
        }
    }
}

// ---------------- persistent LSTM recurrence ----------------
// 128 CTAs x 256 threads. CTA owns hidden units [hs, hs+8); 32 gate rows of w_hh.
// Each thread holds 4 rows x 32 cols of w_hh in registers.
__global__ __launch_bounds__(256, 1) void lstm_kernel(
    const float* __restrict__ w_hh,
    const float* __restrict__ h0, const float* __restrict__ c0,
    float* __restrict__ out)
{
    const int cta = blockIdx.x;          // 0..127
    const int hs = cta * SLICE;
    const int tid = threadIdx.x;
    const int w = tid >> 5;              // warp 0..7
    const int l = tid & 31;              // lane

    // Load persistent weights into registers.
    float wreg[4][32];
#pragma unroll
    for (int i = 0; i < 4; i++) {
        const int lr = 4 * w + i;                       // 0..31
        const int grow = (lr >> 3) * H_DIM + hs + (lr & 7);
        const float* wrow = w_hh + (size_t)grow * H_DIM;
#pragma unroll
        for (int k = 0; k < 32; k++) wreg[i][k] = wrow[l + 32 * k];
    }

    __shared__ float sh_h[H_DIM];
    __shared__ float sh_g[32];
    __shared__ float sh_c[SLICE];

    if (tid < SLICE) sh_c[tid] = c0[hs + tid];
    __syncthreads();

    for (int t = 0; t < T_SEQ; t++) {
        // stage previous h into shared (L2-only load: written by peer CTAs)
        const float* hprev = (t == 0) ? h0 : (g_ys + (size_t)(t - 1) * H_DIM);
        float4 hv4 = __ldcg((const float4*)(hprev + tid * 4));
        *(float4*)(sh_h + tid * 4) = hv4;

        // prefetch gx for the gate lanes (hide L2 latency behind the dot product)
        float gxi = 0.f, gxf = 0.f, gxg = 0.f, gxo = 0.f;
        if (tid < SLICE) {
            const float* gxt = g_gx + (size_t)t * G4 + hs + tid;
            gxi = __ldcg(gxt + 0 * H_DIM);
            gxf = __ldcg(gxt + 1 * H_DIM);
            gxg = __ldcg(gxt + 2 * H_DIM);
            gxo = __ldcg(gxt + 3 * H_DIM);
        }
        __syncthreads();

        float a0 = 0.f, a1 = 0.f, a2 = 0.f, a3 = 0.f;
#pragma unroll
        for (int k = 0; k < 32; k++) {
            const float hv = sh_h[l + 32 * k];
            a0 = fmaf(wreg[0][k], hv, a0);
            a1 = fmaf(wreg[1][k], hv, a1);
            a2 = fmaf(wreg[2][k], hv, a2);
            a3 = fmaf(wreg[3][k], hv, a3);
        }
#pragma unroll
        for (int off = 16; off > 0; off >>= 1) {
            a0 += __shfl_xor_sync(0xFFFFFFFFu, a0, off);
            a1 += __shfl_xor_sync(0xFFFFFFFFu, a1, off);
            a2 += __shfl_xor_sync(0xFFFFFFFFu, a2, off);
            a3 += __shfl_xor_sync(0xFFFFFFFFu, a3, off);
        }
        if (l == 0) {
            sh_g[4 * w + 0] = a0;
            sh_g[4 * w + 1] = a1;
            sh_g[4 * w + 2] = a2;
            sh_g[4 * w + 3] = a3;
        }
        __syncthreads();

        if (tid < SLICE) {
            const int u = tid;
            const float gi = sh_g[u]      + gxi;
            const float gf = sh_g[8 + u]  + gxf;
            const float gg = sh_g[16 + u] + gxg;
            const float go = sh_g[24 + u] + gxo;
            const float i_ = 1.0f / (1.0f + __expf(-gi));
            const float f_ = 1.0f / (1.0f + __expf(-gf));
            const float g_ = tanhf(gg);
            const float o_ = 1.0f / (1.0f + __expf(-go));
            const float c_ = f_ * sh_c[u] + i_ * g_;
            const float h_ = o_ * tanhf(c_);
            sh_c[u] = c_;
            g_ys[(size_t)t * H_DIM + hs + u] = h_;
            if (t == T_SEQ - 1) {
                out[OFF_HT + hs + u] = h_;
                out[OFF_CT + hs + u] = c_;
            }
        }

        // global barrier: count arrivals, last arriver bumps generation
        if (tid == 0) {
            __threadfence();
            const unsigned arr = atomicAdd(&g_count, 1u);
            if (arr == (unsigned)(NCTA * (t + 1)) - 1u) {
                atomicExch(&g_gen, (unsigned)(t + 1));
            }
            while (*(volatile unsigned*)&g_gen < (unsigned)(t + 1)) { }
            __threadfence();
        }
        __syncthreads();
    }
}

// ---------------- policy head: action_mean + log_std broadcast ----------------
__global__ __launch_bounds__(128) void head_kernel(
    const float* __restrict__ mean_w, const float* __restrict__ mean_b,
    const float* __restrict__ log_std, float* __restrict__ out)
{
    const int t = blockIdx.x;
    const int w = threadIdx.x >> 5;   // output index 0..3
    const int l = threadIdx.x & 31;
    const float* hrow = g_h2 + (size_t)t * H_DIM;
    const float* wrow = mean_w + (size_t)w * H_DIM;
    float s = 0.f;
#pragma unroll
    for (int k = 0; k < H_DIM / 32; k++)
        s = fmaf(hrow[l + 32 * k], wrow[l + 32 * k], s);
#pragma unroll
    for (int off = 16; off > 0; off >>= 1)
        s += __shfl_xor_sync(0xFFFFFFFFu, s, off);
    if (l == 0) {
        out[OFF_MEAN + t * OUT_DIM + w] = s + mean_b[w];
        out[OFF_LSTD + t * OUT_DIM + w] = log_std[w];
    }
}

// ---------------- launch ----------------
extern "C" void kernel_launch(void* const* d_in, const int* in_sizes, int n_in,
                              void* d_out, int out_size)
{
    (void)in_sizes; (void)n_in; (void)out_size;
    const float* x      = (const float*)d_in[0];
    const float* h0     = (const float*)d_in[1];
    const float* c0     = (const float*)d_in[2];
    const float* w_ih   = (const float*)d_in[3];
    const float* w_hh   = (const float*)d_in[4];
    const float* b_ih   = (const float*)d_in[5];
    const float* b_hh   = (const float*)d_in[6];
    const float* fc1_w  = (const float*)d_in[7];
    const float* fc1_b  = (const float*)d_in[8];
    const float* fc2_w  = (const float*)d_in[9];
    const float* fc2_b  = (const float*)d_in[10];
    const float* mean_w = (const float*)d_in[11];
    const float* mean_b = (const float*)d_in[12];
    const float* lstd   = (const float*)d_in[13];
    float* out = (float*)d_out;

    float *gx, *ys, *h1, *h2;
    cudaGetSymbolAddress((void**)&gx, g_gx);
    cudaGetSymbolAddress((void**)&ys, g_ys);
    cudaGetSymbolAddress((void**)&h1, g_h1);
    cudaGetSymbolAddress((void**)&h2, g_h2);

    reset_kernel<<<1, 1>>>();

    // gx = x @ w_ih.T + b_ih + b_hh   [2048, 4096]
    gemm_nt_kernel<<<dim3(G4 / BN, T_SEQ / BM), 256>>>(
        x, w_ih, b_ih, b_hh, gx, T_SEQ, G4, IN_DIM, 0);

    // sequential LSTM
    lstm_kernel<<<NCTA, 256>>>(w_hh, h0, c0, out);

    // h1 = relu(ys @ fc1_w.T + fc1_b)
    gemm_nt_kernel<<<dim3(H_DIM / BN, T_SEQ / BM), 256>>>(
        ys, fc1_w, fc1_b, nullptr, h1, T_SEQ, H_DIM, H_DIM, 1);

    // h2 = relu(h1 @ fc2_w.T + fc2_b)
    gemm_nt_kernel<<<dim3(H_DIM / BN, T_SEQ / BM), 256>>>(
        h1, fc2_w, fc2_b, nullptr, h2, T_SEQ, H_DIM, H_DIM, 1);

    // action_mean / log_std
    head_kernel<<<T_SEQ, 128>>>(mean_w, mean_b, lstd, out);
}